// round 15
// baseline (speedup 1.0000x reference)
#include <cuda_runtime.h>
#include <cuda_fp16.h>
#include <math.h>
#include <stdint.h>

// ---------------------------------------------------------------------------
// LSTM: B=128, T=256, In=512, H=1024, Out=512
// All fp16 GEMM operands stored word-permuted: within each 8-word (k16)
// group, word w -> ((w&3)<<1)|((w>>2)&1)  => mma fragment pairs contiguous.
// Phase 1: GXh = fp16( xh @ Wxph^T + bp )  (fp16 mma, 3-stage cp.async,
//          fully-unrolled k loop, 2 blocks/SM)
// Phase 2: 256x lstm_step_mma (JT=16, M-split 2 -> 128 blocks, 8 warps,
//          3-stage cp.async single-sync, GX/c register prefetch, fast-math
//          fused gate epilogue)
// Phase 3: out = HSh @ W_outh^T + b_out    (fp16 mma, fp32 out)
// ---------------------------------------------------------------------------

#define B_   128
#define T_   256
#define IN_  512
#define H_   1024
#define G4_  4096
#define OUT_ 512
#define M_   (B_ * T_)      // 32768
#define HW   512            // half2 words per H-length row

#define KCW    64           // step k-chunk in half2 words (=128 k)
#define SST    72           // step smem row stride in u32 words
#define NCHUNK (HW / KCW)   // 8
// step dynamic smem: 3 x (h 64*SST + w 64*SST) u32
#define DSM_WORDS (3 * (64 * SST + 64 * SST))
#define DSM_BYTES (DSM_WORDS * 4)

// hgemm dynamic smem: 3 stages x (A 128*HPAD + B 128*HPAD) u32
#define HPAD 24
#define GSM_WORDS (3 * 2 * 128 * HPAD)
#define GSM_BYTES (GSM_WORDS * 4)     // 73728

__device__ uint32_t g_Whh [(size_t)G4_ * HW];     // h-part W, fp16 pairs, permuted
__device__ uint32_t g_Wxph[(size_t)G4_ * (IN_/2)];// x-part W, fp16 pairs, permuted
__device__ uint32_t g_Wouth[(size_t)OUT_ * HW];   // out W, fp16 pairs, permuted
__device__ float    g_bp  [G4_];                  // packed bias
__device__ uint32_t g_xh  [(size_t)M_ * (IN_/2)]; // x fp16 pairs, permuted
__device__ uint32_t g_GXh [(size_t)M_ * (G4_/2)]; // gates, fp16 pairs, natural
__device__ uint32_t g_HSh [(size_t)M_ * HW];      // hidden states fp16, permuted
__device__ uint32_t g_hth [2][B_ * HW];           // ping-pong h fp16, permuted
__device__ float    g_c   [B_ * H_];              // cell state

// fast-math activations (MUFU.EX2 path; rel err ~1e-6, << fp16 operand error)
__device__ __forceinline__ float sigmf(float x)  { return 1.0f / (1.0f + __expf(-x)); }
__device__ __forceinline__ float tanhff(float x) { return 2.0f / (1.0f + __expf(-2.0f * x)) - 1.0f; }

// word permutation within each 8-word (k16) group: pair (t, t+4) -> (2t, 2t+1)
__device__ __forceinline__ int wperm(int w) {
    return (w & ~7) | (((w & 3) << 1) | ((w >> 2) & 1));
}

__device__ __forceinline__ void mma_f16(float c[4], uint32_t a0, uint32_t a1,
                                        uint32_t a2, uint32_t a3,
                                        uint32_t b0, uint32_t b1) {
    asm volatile(
        "mma.sync.aligned.m16n8k16.row.col.f32.f16.f16.f32 "
        "{%0,%1,%2,%3}, {%4,%5,%6,%7}, {%8,%9}, {%0,%1,%2,%3};"
        : "+f"(c[0]), "+f"(c[1]), "+f"(c[2]), "+f"(c[3])
        : "r"(a0), "r"(a1), "r"(a2), "r"(a3), "r"(b0), "r"(b1));
}

__device__ __forceinline__ void cp_async16(void* smem_dst, const void* gmem_src) {
    uint32_t d = (uint32_t)__cvta_generic_to_shared(smem_dst);
    asm volatile("cp.async.cg.shared.global [%0], [%1], 16;"
                 :: "r"(d), "l"(gmem_src));
}
__device__ __forceinline__ void cp_commit() {
    asm volatile("cp.async.commit_group;");
}
template <int N>
__device__ __forceinline__ void cp_wait() {
    asm volatile("cp.async.wait_group %0;" :: "n"(N));
}

// ---------------------------------------------------------------------------
// Phase 0a: pack weights. blockIdx.x = n (0..4095). 128 threads.
// ---------------------------------------------------------------------------
__global__ void pack_weights(const float* __restrict__ Wf, const float* __restrict__ Wi,
                             const float* __restrict__ Wc, const float* __restrict__ Wo,
                             const float* __restrict__ bf, const float* __restrict__ bi,
                             const float* __restrict__ bc, const float* __restrict__ bo)
{
    int n = blockIdx.x;
    int g = n >> 10;
    int j = n & 1023;
    const float* W = (g == 0) ? Wf : (g == 1) ? Wi : (g == 2) ? Wc : Wo;
    const float* row = W + (size_t)j * (IN_ + H_);
    for (int w = threadIdx.x; w < IN_ / 2; w += blockDim.x) {
        __half2 v = __floats2half2_rn(row[2 * w], row[2 * w + 1]);
        g_Wxph[(size_t)n * (IN_ / 2) + wperm(w)] = *(uint32_t*)&v;
    }
    for (int w = threadIdx.x; w < HW; w += blockDim.x) {
        __half2 v = __floats2half2_rn(row[IN_ + 2 * w], row[IN_ + 2 * w + 1]);
        g_Whh[(size_t)n * HW + wperm(w)] = *(uint32_t*)&v;
    }
    if (threadIdx.x == 0) {
        const float* bb = (g == 0) ? bf : (g == 1) ? bi : (g == 2) ? bc : bo;
        g_bp[n] = bb[j];
    }
}

// ---------------------------------------------------------------------------
// Phase 0b: fp32 -> fp16 convert with word permutation.
// ---------------------------------------------------------------------------
__global__ void cvt_f2h_perm(const float* __restrict__ in, uint32_t* __restrict__ out,
                             int nW)
{
    int w = blockIdx.x * blockDim.x + threadIdx.x;
    if (w < nW) {
        __half2 v = __floats2half2_rn(in[2 * w], in[2 * w + 1]);
        out[(w & ~7) | (((w & 3) << 1) | ((w >> 2) & 1))] = *(uint32_t*)&v;
    }
}

// ---------------------------------------------------------------------------
// Phases 1 & 3: fp16 NT GEMM, fp32 accum, permuted operands.
// 3-stage cp.async pipeline in dynamic smem, one sync per k-chunk,
// K fully unrolled via template (KWT = K/2 words).
// ---------------------------------------------------------------------------
template <int OUT16, int KWT>
__global__ void __launch_bounds__(256, 2)
hgemm_nt(const uint32_t* __restrict__ A, const uint32_t* __restrict__ Bm,
         const float* __restrict__ bias, void* __restrict__ Cv, int Ndim)
{
    extern __shared__ uint32_t gsm[];
    uint32_t* sA[3] = { gsm,                  gsm + 128 * HPAD,     gsm + 2 * 128 * HPAD };
    uint32_t* sB[3] = { gsm + 3 * 128 * HPAD, gsm + 4 * 128 * HPAD, gsm + 5 * 128 * HPAD };

    const int tid  = threadIdx.x;
    const int m0   = blockIdx.y * 128;
    const int n0   = blockIdx.x * 128;
    const int lane = tid & 31;
    const int warp = tid >> 5;
    const int wm   = warp >> 1;
    const int wn   = warp & 1;
    const int g    = lane >> 2;
    const int t    = lane & 3;

    const int row  = tid >> 1;
    const int half = tid & 1;

    const uint32_t* Arow = A + (size_t)(m0 + row) * KWT + half * 8;
    const uint32_t* Brow = Bm + (size_t)(n0 + row) * KWT + half * 8;
    const int soff = row * HPAD + half * 8;

    constexpr int NIT = KWT / 16;    // 16 words = 32 k per iteration

    float acc[2][8][4];
#pragma unroll
    for (int mf = 0; mf < 2; mf++)
#pragma unroll
        for (int nf = 0; nf < 8; nf++)
#pragma unroll
            for (int i = 0; i < 4; i++) acc[mf][nf][i] = 0.0f;

    auto stage = [&](int it, int bi) {
        const uint32_t* a = Arow + it * 16;
        const uint32_t* b = Brow + it * 16;
        cp_async16(&sA[bi][soff],     a);
        cp_async16(&sA[bi][soff + 4], a + 4);
        cp_async16(&sB[bi][soff],     b);
        cp_async16(&sB[bi][soff + 4], b + 4);
        cp_commit();
    };

    stage(0, 0);
    stage(1, 1);

#pragma unroll
    for (int it = 0; it < NIT; it++) {
        if (it == NIT - 1) cp_wait<0>(); else cp_wait<1>();
        __syncthreads();
        if (it + 2 < NIT) stage(it + 2, (it + 2) % 3);

        const uint32_t* cA = sA[it % 3];
        const uint32_t* cB = sB[it % 3];

#pragma unroll
        for (int ks = 0; ks < 2; ks++) {        // two k16 steps
            const int kb = ks * 8 + 2 * t;
            uint2 a[2][2];
#pragma unroll
            for (int mf = 0; mf < 2; mf++) {
                const int ar = wm * 32 + mf * 16;
                a[mf][0] = *(const uint2*)&cA[(ar + g)     * HPAD + kb]; // (a0,a2)
                a[mf][1] = *(const uint2*)&cA[(ar + g + 8) * HPAD + kb]; // (a1,a3)
            }
#pragma unroll
            for (int nf = 0; nf < 8; nf++) {
                const int br = wn * 64 + nf * 8 + g;
                uint2 bv = *(const uint2*)&cB[br * HPAD + kb];           // (b0,b1)
#pragma unroll
                for (int mf = 0; mf < 2; mf++)
                    mma_f16(acc[mf][nf], a[mf][0].x, a[mf][1].x,
                            a[mf][0].y, a[mf][1].y, bv.x, bv.y);
            }
        }
    }

#pragma unroll
    for (int mf = 0; mf < 2; mf++) {
        const int rbase = m0 + wm * 32 + mf * 16;
#pragma unroll
        for (int nf = 0; nf < 8; nf++) {
            const int cbase = n0 + wn * 64 + nf * 8 + 2 * t;
            float bv0 = bias[cbase];
            float bv1 = bias[cbase + 1];
            float v00 = acc[mf][nf][0] + bv0, v01 = acc[mf][nf][1] + bv1;
            float v10 = acc[mf][nf][2] + bv0, v11 = acc[mf][nf][3] + bv1;
            if (OUT16) {
                uint32_t* C = (uint32_t*)Cv;
                __half2 h0 = __floats2half2_rn(v00, v01);
                __half2 h1 = __floats2half2_rn(v10, v11);
                C[((size_t)(rbase + g) * Ndim + cbase) >> 1]     = *(uint32_t*)&h0;
                C[((size_t)(rbase + g + 8) * Ndim + cbase) >> 1] = *(uint32_t*)&h1;
            } else {
                float* C = (float*)Cv;
                *(float2*)&C[(size_t)(rbase + g) * Ndim + cbase]     = make_float2(v00, v01);
                *(float2*)&C[(size_t)(rbase + g + 8) * Ndim + cbase] = make_float2(v10, v11);
            }
        }
    }
}

// ---------------------------------------------------------------------------
// Phase 2: one timestep, fp16 m16n8k16. JT=16, M-split 2:
// grid = (64 j-tiles, 2 m-halves) = 128 blocks, 256 threads (8 warps).
// GX + c prefetched into registers before the mainloop (latency overlapped
// with all 8 chunks). Fast-math epilogue.
// ---------------------------------------------------------------------------
__global__ void __launch_bounds__(256)
lstm_step_mma(int t)
{
    extern __shared__ uint32_t dsm[];
    uint32_t* hb[3] = { dsm, dsm + 64 * SST, dsm + 2 * 64 * SST };
    uint32_t* wbase = dsm + 3 * 64 * SST;
    uint32_t* wb[3] = { wbase, wbase + 64 * SST, wbase + 2 * 64 * SST };

    const int tid  = threadIdx.x;
    const int lane = tid & 31;
    const int warp = tid >> 5;          // 0..7
    const int j0   = blockIdx.x * 16;
    const int mbase = blockIdx.y * 64;

    const uint32_t* __restrict__ ht_in = g_hth[t & 1];
    uint32_t* __restrict__ ht_out      = g_hth[(t + 1) & 1];

    const int wm = warp & 3;            // m sub-tile
    const int u0 = warp >> 2;           // j half
    const int r  = lane >> 2;           // 0..7
    const int kq = lane & 3;            // 0..3

    float acc[4][4];
#pragma unroll
    for (int g = 0; g < 4; g++)
#pragma unroll
        for (int i = 0; i < 4; i++) acc[g][i] = 0.0f;

    // ---- register prefetch of GX (16 words) and c (4 float2); these LDGs
    // issue now and complete during the mainloop ----
    uint32_t gxr[2][2][4];   // [rh][u][gate]
    float2   cr [2][2];      // [rh][u]
#pragma unroll
    for (int rh = 0; rh < 2; rh++) {
        const int b = mbase + wm * 16 + r + rh * 8;
        const size_t m = (size_t)b * T_ + t;
        const uint32_t* gxw = g_GXh + m * (G4_ / 2);
#pragma unroll
        for (int u = 0; u < 2; u++) {
            const int jcu = j0 + 8 * u + 2 * kq;
#pragma unroll
            for (int g = 0; g < 4; g++)
                gxr[rh][u][g] = gxw[(g * H_ + jcu) >> 1];
            cr[rh][u] = *(const float2*)(g_c + b * H_ + jcu);
        }
    }

    auto stage = [&](int c, int bi) {
        const int k0w = c * KCW;
        // h: 64 rows x 64 words = 1024 16B segs, 4 per thread
#pragma unroll
        for (int i = 0; i < 4; i++) {
            int s    = tid + 256 * i;
            int row  = s >> 4;
            int col4 = (s & 15) * 4;
            cp_async16(&hb[bi][row * SST + col4],
                       ht_in + (size_t)(mbase + row) * HW + k0w + col4);
        }
        // W: 64 rows (u, gate, jj) x 64 words = 1024 segs, 4 per thread
#pragma unroll
        for (int i = 0; i < 4; i++) {
            int s    = tid + 256 * i;
            int row  = s >> 4;          // 0..63
            int col4 = (s & 15) * 4;
            int wu   = row >> 5;        // j half
            int wg   = (row >> 3) & 3;  // gate
            int jj   = row & 7;
            cp_async16(&wb[bi][row * SST + col4],
                       g_Whh + (size_t)(wg * H_ + j0 + 8 * wu + jj) * HW + k0w + col4);
        }
        cp_commit();
    };

    stage(0, 0);
    stage(1, 1);

    for (int c = 0; c < NCHUNK; c++) {
        if (c == NCHUNK - 1) cp_wait<0>(); else cp_wait<1>();
        __syncthreads();
        if (c + 2 < NCHUNK) stage(c + 2, (c + 2) % 3);

        const uint32_t* hbuf = hb[c % 3];
        const uint32_t* wbuf = wb[c % 3];
        const int arow0 = (wm * 16 + r) * SST;
        const int arow1 = (wm * 16 + r + 8) * SST;
        const int wrow  = u0 * 32 + r;

#pragma unroll
        for (int ks = 0; ks < 8; ks++) {        // 8 k16 groups per chunk
            const int kb = ks * 8 + 2 * kq;
            uint2 aA = *(const uint2*)&hbuf[arow0 + kb];   // (a0, a2)
            uint2 aB = *(const uint2*)&hbuf[arow1 + kb];   // (a1, a3)
#pragma unroll
            for (int g = 0; g < 4; g++) {
                uint2 bv = *(const uint2*)&wbuf[(wrow + g * 8) * SST + kb];
                mma_f16(acc[g], aA.x, aB.x, aA.y, aB.y, bv.x, bv.y);
            }
        }
    }

    // NOTE: warp u0 computed gates for j half u0 only; acc[g] maps to
    // columns jc = j0 + 8*u0 + 2*kq. Use prefetched gxr/cr at index u0.
    const int jc = j0 + 8 * u0 + 2 * kq;
    const int wn = jc >> 1;                     // natural word index
    const int pw = wperm(wn);                   // permuted word index
#pragma unroll
    for (int rh = 0; rh < 2; rh++) {
        const int b = mbase + wm * 16 + r + rh * 8;
        const size_t m = (size_t)b * T_ + t;
        float2 gxf = __half22float2(*(__half2*)&gxr[rh][u0][0]);
        float2 gxi = __half22float2(*(__half2*)&gxr[rh][u0][1]);
        float2 gxc = __half22float2(*(__half2*)&gxr[rh][u0][2]);
        float2 gxo = __half22float2(*(__half2*)&gxr[rh][u0][3]);
        float2 cold = cr[rh][u0];

        const int a0i = rh * 2, a1i = rh * 2 + 1;
        float f0 = sigmf(acc[0][a0i] + gxf.x);
        float f1 = sigmf(acc[0][a1i] + gxf.y);
        float i0 = sigmf(acc[1][a0i] + gxi.x);
        float i1 = sigmf(acc[1][a1i] + gxi.y);
        float t0 = tanhff(acc[2][a0i] + gxc.x);
        float t1 = tanhff(acc[2][a1i] + gxc.y);
        float o0 = sigmf(acc[3][a0i] + gxo.x);
        float o1 = sigmf(acc[3][a1i] + gxo.y);

        float cn0 = f0 * cold.x + i0 * t0;
        float cn1 = f1 * cold.y + i1 * t1;
        float hn0 = o0 * tanhff(cn0);
        float hn1 = o1 * tanhff(cn1);

        *(float2*)(g_c + b * H_ + jc) = make_float2(cn0, cn1);

        __half2 hp = __floats2half2_rn(hn0, hn1);
        g_HSh[m * HW + pw]          = *(uint32_t*)&hp;   // permuted (P3 operand)
        ht_out[(size_t)b * HW + pw] = *(uint32_t*)&hp;   // permuted (next step A)
    }
}

// ---------------------------------------------------------------------------
// Host launcher
// ---------------------------------------------------------------------------
extern "C" void kernel_launch(void* const* d_in, const int* in_sizes, int n_in,
                              void* d_out, int out_size)
{
    (void)in_sizes; (void)n_in; (void)out_size;

    const float* x     = (const float*)d_in[0];
    const float* W_f   = (const float*)d_in[1];
    const float* b_f   = (const float*)d_in[2];
    const float* W_i   = (const float*)d_in[3];
    const float* b_i   = (const float*)d_in[4];
    const float* W_c   = (const float*)d_in[5];
    const float* b_c   = (const float*)d_in[6];
    const float* W_o   = (const float*)d_in[7];
    const float* b_o   = (const float*)d_in[8];
    const float* W_out = (const float*)d_in[9];
    const float* b_out = (const float*)d_in[10];
    float* out = (float*)d_out;

    void *p_wxph, *p_wouth, *p_bp, *p_xh, *p_gxh, *p_hsh, *p_ht, *p_c;
    cudaGetSymbolAddress(&p_wxph,  g_Wxph);
    cudaGetSymbolAddress(&p_wouth, g_Wouth);
    cudaGetSymbolAddress(&p_bp,    g_bp);
    cudaGetSymbolAddress(&p_xh,    g_xh);
    cudaGetSymbolAddress(&p_gxh,   g_GXh);
    cudaGetSymbolAddress(&p_hsh,   g_HSh);
    cudaGetSymbolAddress(&p_ht,    g_hth);
    cudaGetSymbolAddress(&p_c,     g_c);

    cudaFuncSetAttribute(lstm_step_mma,
                         cudaFuncAttributeMaxDynamicSharedMemorySize,
                         DSM_BYTES);
    cudaFuncSetAttribute((hgemm_nt<1, IN_/2>),
                         cudaFuncAttributeMaxDynamicSharedMemorySize,
                         GSM_BYTES);
    cudaFuncSetAttribute((hgemm_nt<0, HW>),
                         cudaFuncAttributeMaxDynamicSharedMemorySize,
                         GSM_BYTES);

    // zero initial state; t=255 writes g_hth[0], re-zeroed on every replay.
    cudaMemsetAsync(p_ht, 0, (size_t)B_ * HW * sizeof(uint32_t));
    cudaMemsetAsync(p_c,  0, (size_t)B_ * H_ * sizeof(float));

    // Phase 0: pack weights + permuting fp16 converts for x and W_out
    pack_weights<<<G4_, 128>>>(W_f, W_i, W_c, W_o, b_f, b_i, b_c, b_o);
    {
        int nW = M_ * IN_ / 2;
        cvt_f2h_perm<<<(nW + 255) / 256, 256>>>(x, (uint32_t*)p_xh, nW);
        int wW = OUT_ * H_ / 2;
        cvt_f2h_perm<<<(wW + 255) / 256, 256>>>(W_out, (uint32_t*)p_wouth, wW);
    }

    // Phase 1: GXh = fp16( xh @ Wxph^T + bp )
    {
        dim3 grid(G4_ / 128, M_ / 128);
        hgemm_nt<1, IN_/2><<<grid, 256, GSM_BYTES>>>((const uint32_t*)p_xh,
                                                     (const uint32_t*)p_wxph,
                                                     (const float*)p_bp, p_gxh,
                                                     G4_);
    }

    // Phase 2: 256 recurrent steps (fp16 mma, JT=16 x Msplit=2, 3-stage)
    for (int t = 0; t < T_; t++) {
        dim3 grid(H_ / 16, 2);
        lstm_step_mma<<<grid, 256, DSM_BYTES>>>(t);
    }

    // Phase 3: out = HSh @ W_outh^T + b_out  (fp32 out)
    {
        dim3 grid(OUT_ / 128, M_ / 128);
        hgemm_nt<0, HW><<<grid, 256, GSM_BYTES>>>((const uint32_t*)p_hsh,
                                                  (const uint32_t*)p_wouth,
                                                  b_out, out, OUT_);
    }
}

// round 17
// speedup vs baseline: 1.0720x; 1.0720x over previous
#include <cuda_runtime.h>
#include <cuda_fp16.h>
#include <math.h>
#include <stdint.h>

// ---------------------------------------------------------------------------
// LSTM: B=128, T=256, In=512, H=1024, Out=512
// All fp16 GEMM operands stored word-permuted: within each 8-word (k16)
// group, word w -> ((w&3)<<1)|((w>>2)&1)  => mma fragment pairs contiguous.
// Phase 1: GXh = fp16( xh @ Wxph^T + bp )  (fp16 mma, 3-stage cp.async,
//          fully-unrolled k loop, 2 blocks/SM)
// Phase 2: 256x lstm_step_mma (JT=16, M-split 2 -> 128 blocks, 8 warps,
//          3-stage cp.async single-sync, u0-only GX/c register prefetch,
//          fast-math fused gate epilogue)
// Phase 3: out = HSh @ W_outh^T + b_out    (fp16 mma, fp32 out)
// ---------------------------------------------------------------------------

#define B_   128
#define T_   256
#define IN_  512
#define H_   1024
#define G4_  4096
#define OUT_ 512
#define M_   (B_ * T_)      // 32768
#define HW   512            // half2 words per H-length row

#define KCW    64           // step k-chunk in half2 words (=128 k)
#define SST    72           // step smem row stride in u32 words
#define NCHUNK (HW / KCW)   // 8
// step dynamic smem: 3 x (h 64*SST + w 64*SST) u32
#define DSM_WORDS (3 * (64 * SST + 64 * SST))
#define DSM_BYTES (DSM_WORDS * 4)

// hgemm dynamic smem: 3 stages x (A 128*HPAD + B 128*HPAD) u32
#define HPAD 24
#define GSM_WORDS (3 * 2 * 128 * HPAD)
#define GSM_BYTES (GSM_WORDS * 4)     // 73728

__device__ uint32_t g_Whh [(size_t)G4_ * HW];     // h-part W, fp16 pairs, permuted
__device__ uint32_t g_Wxph[(size_t)G4_ * (IN_/2)];// x-part W, fp16 pairs, permuted
__device__ uint32_t g_Wouth[(size_t)OUT_ * HW];   // out W, fp16 pairs, permuted
__device__ float    g_bp  [G4_];                  // packed bias
__device__ uint32_t g_xh  [(size_t)M_ * (IN_/2)]; // x fp16 pairs, permuted
__device__ uint32_t g_GXh [(size_t)M_ * (G4_/2)]; // gates, fp16 pairs, natural
__device__ uint32_t g_HSh [(size_t)M_ * HW];      // hidden states fp16, permuted
__device__ uint32_t g_hth [2][B_ * HW];           // ping-pong h fp16, permuted
__device__ float    g_c   [B_ * H_];              // cell state

// fast-math activations (MUFU.EX2 path; rel err ~1e-6, << fp16 operand error)
__device__ __forceinline__ float sigmf(float x)  { return 1.0f / (1.0f + __expf(-x)); }
__device__ __forceinline__ float tanhff(float x) { return 2.0f / (1.0f + __expf(-2.0f * x)) - 1.0f; }

// word permutation within each 8-word (k16) group: pair (t, t+4) -> (2t, 2t+1)
__device__ __forceinline__ int wperm(int w) {
    return (w & ~7) | (((w & 3) << 1) | ((w >> 2) & 1));
}

__device__ __forceinline__ void mma_f16(float c[4], uint32_t a0, uint32_t a1,
                                        uint32_t a2, uint32_t a3,
                                        uint32_t b0, uint32_t b1) {
    asm volatile(
        "mma.sync.aligned.m16n8k16.row.col.f32.f16.f16.f32 "
        "{%0,%1,%2,%3}, {%4,%5,%6,%7}, {%8,%9}, {%0,%1,%2,%3};"
        : "+f"(c[0]), "+f"(c[1]), "+f"(c[2]), "+f"(c[3])
        : "r"(a0), "r"(a1), "r"(a2), "r"(a3), "r"(b0), "r"(b1));
}

__device__ __forceinline__ void cp_async16(void* smem_dst, const void* gmem_src) {
    uint32_t d = (uint32_t)__cvta_generic_to_shared(smem_dst);
    asm volatile("cp.async.cg.shared.global [%0], [%1], 16;"
                 :: "r"(d), "l"(gmem_src));
}
__device__ __forceinline__ void cp_commit() {
    asm volatile("cp.async.commit_group;");
}
template <int N>
__device__ __forceinline__ void cp_wait() {
    asm volatile("cp.async.wait_group %0;" :: "n"(N));
}

// ---------------------------------------------------------------------------
// Phase 0a: pack weights. blockIdx.x = n (0..4095). 128 threads.
// ---------------------------------------------------------------------------
__global__ void pack_weights(const float* __restrict__ Wf, const float* __restrict__ Wi,
                             const float* __restrict__ Wc, const float* __restrict__ Wo,
                             const float* __restrict__ bf, const float* __restrict__ bi,
                             const float* __restrict__ bc, const float* __restrict__ bo)
{
    int n = blockIdx.x;
    int g = n >> 10;
    int j = n & 1023;
    const float* W = (g == 0) ? Wf : (g == 1) ? Wi : (g == 2) ? Wc : Wo;
    const float* row = W + (size_t)j * (IN_ + H_);
    for (int w = threadIdx.x; w < IN_ / 2; w += blockDim.x) {
        __half2 v = __floats2half2_rn(row[2 * w], row[2 * w + 1]);
        g_Wxph[(size_t)n * (IN_ / 2) + wperm(w)] = *(uint32_t*)&v;
    }
    for (int w = threadIdx.x; w < HW; w += blockDim.x) {
        __half2 v = __floats2half2_rn(row[IN_ + 2 * w], row[IN_ + 2 * w + 1]);
        g_Whh[(size_t)n * HW + wperm(w)] = *(uint32_t*)&v;
    }
    if (threadIdx.x == 0) {
        const float* bb = (g == 0) ? bf : (g == 1) ? bi : (g == 2) ? bc : bo;
        g_bp[n] = bb[j];
    }
}

// ---------------------------------------------------------------------------
// Phase 0b: fp32 -> fp16 convert with word permutation.
// ---------------------------------------------------------------------------
__global__ void cvt_f2h_perm(const float* __restrict__ in, uint32_t* __restrict__ out,
                             int nW)
{
    int w = blockIdx.x * blockDim.x + threadIdx.x;
    if (w < nW) {
        __half2 v = __floats2half2_rn(in[2 * w], in[2 * w + 1]);
        out[(w & ~7) | (((w & 3) << 1) | ((w >> 2) & 1))] = *(uint32_t*)&v;
    }
}

// ---------------------------------------------------------------------------
// Phases 1 & 3: fp16 NT GEMM, fp32 accum, permuted operands.
// 3-stage cp.async pipeline in dynamic smem, one sync per k-chunk,
// K fully unrolled via template (KWT = K/2 words).
// ---------------------------------------------------------------------------
template <int OUT16, int KWT>
__global__ void __launch_bounds__(256, 2)
hgemm_nt(const uint32_t* __restrict__ A, const uint32_t* __restrict__ Bm,
         const float* __restrict__ bias, void* __restrict__ Cv, int Ndim)
{
    extern __shared__ uint32_t gsm[];
    uint32_t* sA[3] = { gsm,                  gsm + 128 * HPAD,     gsm + 2 * 128 * HPAD };
    uint32_t* sB[3] = { gsm + 3 * 128 * HPAD, gsm + 4 * 128 * HPAD, gsm + 5 * 128 * HPAD };

    const int tid  = threadIdx.x;
    const int m0   = blockIdx.y * 128;
    const int n0   = blockIdx.x * 128;
    const int lane = tid & 31;
    const int warp = tid >> 5;
    const int wm   = warp >> 1;
    const int wn   = warp & 1;
    const int g    = lane >> 2;
    const int t    = lane & 3;

    const int row  = tid >> 1;
    const int half = tid & 1;

    const uint32_t* Arow = A + (size_t)(m0 + row) * KWT + half * 8;
    const uint32_t* Brow = Bm + (size_t)(n0 + row) * KWT + half * 8;
    const int soff = row * HPAD + half * 8;

    constexpr int NIT = KWT / 16;    // 16 words = 32 k per iteration

    float acc[2][8][4];
#pragma unroll
    for (int mf = 0; mf < 2; mf++)
#pragma unroll
        for (int nf = 0; nf < 8; nf++)
#pragma unroll
            for (int i = 0; i < 4; i++) acc[mf][nf][i] = 0.0f;

    auto stage = [&](int it, int bi) {
        const uint32_t* a = Arow + it * 16;
        const uint32_t* b = Brow + it * 16;
        cp_async16(&sA[bi][soff],     a);
        cp_async16(&sA[bi][soff + 4], a + 4);
        cp_async16(&sB[bi][soff],     b);
        cp_async16(&sB[bi][soff + 4], b + 4);
        cp_commit();
    };

    stage(0, 0);
    stage(1, 1);

#pragma unroll
    for (int it = 0; it < NIT; it++) {
        if (it == NIT - 1) cp_wait<0>(); else cp_wait<1>();
        __syncthreads();
        if (it + 2 < NIT) stage(it + 2, (it + 2) % 3);

        const uint32_t* cA = sA[it % 3];
        const uint32_t* cB = sB[it % 3];

#pragma unroll
        for (int ks = 0; ks < 2; ks++) {        // two k16 steps
            const int kb = ks * 8 + 2 * t;
            uint2 a[2][2];
#pragma unroll
            for (int mf = 0; mf < 2; mf++) {
                const int ar = wm * 32 + mf * 16;
                a[mf][0] = *(const uint2*)&cA[(ar + g)     * HPAD + kb]; // (a0,a2)
                a[mf][1] = *(const uint2*)&cA[(ar + g + 8) * HPAD + kb]; // (a1,a3)
            }
#pragma unroll
            for (int nf = 0; nf < 8; nf++) {
                const int br = wn * 64 + nf * 8 + g;
                uint2 bv = *(const uint2*)&cB[br * HPAD + kb];           // (b0,b1)
#pragma unroll
                for (int mf = 0; mf < 2; mf++)
                    mma_f16(acc[mf][nf], a[mf][0].x, a[mf][1].x,
                            a[mf][0].y, a[mf][1].y, bv.x, bv.y);
            }
        }
    }

#pragma unroll
    for (int mf = 0; mf < 2; mf++) {
        const int rbase = m0 + wm * 32 + mf * 16;
#pragma unroll
        for (int nf = 0; nf < 8; nf++) {
            const int cbase = n0 + wn * 64 + nf * 8 + 2 * t;
            float bv0 = bias[cbase];
            float bv1 = bias[cbase + 1];
            float v00 = acc[mf][nf][0] + bv0, v01 = acc[mf][nf][1] + bv1;
            float v10 = acc[mf][nf][2] + bv0, v11 = acc[mf][nf][3] + bv1;
            if (OUT16) {
                uint32_t* C = (uint32_t*)Cv;
                __half2 h0 = __floats2half2_rn(v00, v01);
                __half2 h1 = __floats2half2_rn(v10, v11);
                C[((size_t)(rbase + g) * Ndim + cbase) >> 1]     = *(uint32_t*)&h0;
                C[((size_t)(rbase + g + 8) * Ndim + cbase) >> 1] = *(uint32_t*)&h1;
            } else {
                float* C = (float*)Cv;
                *(float2*)&C[(size_t)(rbase + g) * Ndim + cbase]     = make_float2(v00, v01);
                *(float2*)&C[(size_t)(rbase + g + 8) * Ndim + cbase] = make_float2(v10, v11);
            }
        }
    }
}

// ---------------------------------------------------------------------------
// Phase 2: one timestep, fp16 m16n8k16. JT=16, M-split 2:
// grid = (64 j-tiles, 2 m-halves) = 128 blocks, 256 threads (8 warps).
// GX + c for THIS warp's j-half only prefetched into registers before the
// mainloop. Fast-math epilogue.
// ---------------------------------------------------------------------------
__global__ void __launch_bounds__(256)
lstm_step_mma(int t)
{
    extern __shared__ uint32_t dsm[];
    uint32_t* hb[3] = { dsm, dsm + 64 * SST, dsm + 2 * 64 * SST };
    uint32_t* wbase = dsm + 3 * 64 * SST;
    uint32_t* wb[3] = { wbase, wbase + 64 * SST, wbase + 2 * 64 * SST };

    const int tid  = threadIdx.x;
    const int lane = tid & 31;
    const int warp = tid >> 5;          // 0..7
    const int j0   = blockIdx.x * 16;
    const int mbase = blockIdx.y * 64;

    const uint32_t* __restrict__ ht_in = g_hth[t & 1];
    uint32_t* __restrict__ ht_out      = g_hth[(t + 1) & 1];

    const int wm = warp & 3;            // m sub-tile
    const int u0 = warp >> 2;           // j half
    const int r  = lane >> 2;           // 0..7
    const int kq = lane & 3;            // 0..3
    const int jc = j0 + 8 * u0 + 2 * kq;

    float acc[4][4];
#pragma unroll
    for (int g = 0; g < 4; g++)
#pragma unroll
        for (int i = 0; i < 4; i++) acc[g][i] = 0.0f;

    // ---- register prefetch of THIS warp's GX (8 words) and c (2 float2);
    // LDGs issue now, complete during the mainloop ----
    uint32_t gxr[2][4];   // [rh][gate]
    float2   cr [2];      // [rh]
#pragma unroll
    for (int rh = 0; rh < 2; rh++) {
        const int b = mbase + wm * 16 + r + rh * 8;
        const size_t m = (size_t)b * T_ + t;
        const uint32_t* gxw = g_GXh + m * (G4_ / 2);
#pragma unroll
        for (int g = 0; g < 4; g++)
            gxr[rh][g] = gxw[(g * H_ + jc) >> 1];
        cr[rh] = *(const float2*)(g_c + b * H_ + jc);
    }

    auto stage = [&](int c, int bi) {
        const int k0w = c * KCW;
        // h: 64 rows x 64 words = 1024 16B segs, 4 per thread
#pragma unroll
        for (int i = 0; i < 4; i++) {
            int s    = tid + 256 * i;
            int row  = s >> 4;
            int col4 = (s & 15) * 4;
            cp_async16(&hb[bi][row * SST + col4],
                       ht_in + (size_t)(mbase + row) * HW + k0w + col4);
        }
        // W: 64 rows (u, gate, jj) x 64 words = 1024 segs, 4 per thread
#pragma unroll
        for (int i = 0; i < 4; i++) {
            int s    = tid + 256 * i;
            int row  = s >> 4;          // 0..63
            int col4 = (s & 15) * 4;
            int wu   = row >> 5;        // j half
            int wg   = (row >> 3) & 3;  // gate
            int jj   = row & 7;
            cp_async16(&wb[bi][row * SST + col4],
                       g_Whh + (size_t)(wg * H_ + j0 + 8 * wu + jj) * HW + k0w + col4);
        }
        cp_commit();
    };

    stage(0, 0);
    stage(1, 1);

    for (int c = 0; c < NCHUNK; c++) {
        if (c == NCHUNK - 1) cp_wait<0>(); else cp_wait<1>();
        __syncthreads();
        if (c + 2 < NCHUNK) stage(c + 2, (c + 2) % 3);

        const uint32_t* hbuf = hb[c % 3];
        const uint32_t* wbuf = wb[c % 3];
        const int arow0 = (wm * 16 + r) * SST;
        const int arow1 = (wm * 16 + r + 8) * SST;
        const int wrow  = u0 * 32 + r;

#pragma unroll
        for (int ks = 0; ks < 8; ks++) {        // 8 k16 groups per chunk
            const int kb = ks * 8 + 2 * kq;
            uint2 aA = *(const uint2*)&hbuf[arow0 + kb];   // (a0, a2)
            uint2 aB = *(const uint2*)&hbuf[arow1 + kb];   // (a1, a3)
#pragma unroll
            for (int g = 0; g < 4; g++) {
                uint2 bv = *(const uint2*)&wbuf[(wrow + g * 8) * SST + kb];
                mma_f16(acc[g], aA.x, aB.x, aA.y, aB.y, bv.x, bv.y);
            }
        }
    }

    // fused gate epilogue: lane holds rows {mbase+16wm+r, +8}, cols {jc, jc+1}
    const int wn = jc >> 1;                     // natural word index
    const int pw = wperm(wn);                   // permuted word index
#pragma unroll
    for (int rh = 0; rh < 2; rh++) {
        const int b = mbase + wm * 16 + r + rh * 8;
        const size_t m = (size_t)b * T_ + t;
        float2 gxf = __half22float2(*(__half2*)&gxr[rh][0]);
        float2 gxi = __half22float2(*(__half2*)&gxr[rh][1]);
        float2 gxc = __half22float2(*(__half2*)&gxr[rh][2]);
        float2 gxo = __half22float2(*(__half2*)&gxr[rh][3]);
        float2 cold = cr[rh];

        const int a0i = rh * 2, a1i = rh * 2 + 1;
        float f0 = sigmf(acc[0][a0i] + gxf.x);
        float f1 = sigmf(acc[0][a1i] + gxf.y);
        float i0 = sigmf(acc[1][a0i] + gxi.x);
        float i1 = sigmf(acc[1][a1i] + gxi.y);
        float t0 = tanhff(acc[2][a0i] + gxc.x);
        float t1 = tanhff(acc[2][a1i] + gxc.y);
        float o0 = sigmf(acc[3][a0i] + gxo.x);
        float o1 = sigmf(acc[3][a1i] + gxo.y);

        float cn0 = f0 * cold.x + i0 * t0;
        float cn1 = f1 * cold.y + i1 * t1;
        float hn0 = o0 * tanhff(cn0);
        float hn1 = o1 * tanhff(cn1);

        *(float2*)(g_c + b * H_ + jc) = make_float2(cn0, cn1);

        __half2 hp = __floats2half2_rn(hn0, hn1);
        g_HSh[m * HW + pw]          = *(uint32_t*)&hp;   // permuted (P3 operand)
        ht_out[(size_t)b * HW + pw] = *(uint32_t*)&hp;   // permuted (next step A)
    }
}

// ---------------------------------------------------------------------------
// Host launcher
// ---------------------------------------------------------------------------
extern "C" void kernel_launch(void* const* d_in, const int* in_sizes, int n_in,
                              void* d_out, int out_size)
{
    (void)in_sizes; (void)n_in; (void)out_size;

    const float* x     = (const float*)d_in[0];
    const float* W_f   = (const float*)d_in[1];
    const float* b_f   = (const float*)d_in[2];
    const float* W_i   = (const float*)d_in[3];
    const float* b_i   = (const float*)d_in[4];
    const float* W_c   = (const float*)d_in[5];
    const float* b_c   = (const float*)d_in[6];
    const float* W_o   = (const float*)d_in[7];
    const float* b_o   = (const float*)d_in[8];
    const float* W_out = (const float*)d_in[9];
    const float* b_out = (const float*)d_in[10];
    float* out = (float*)d_out;

    void *p_wxph, *p_wouth, *p_bp, *p_xh, *p_gxh, *p_hsh, *p_ht, *p_c;
    cudaGetSymbolAddress(&p_wxph,  g_Wxph);
    cudaGetSymbolAddress(&p_wouth, g_Wouth);
    cudaGetSymbolAddress(&p_bp,    g_bp);
    cudaGetSymbolAddress(&p_xh,    g_xh);
    cudaGetSymbolAddress(&p_gxh,   g_GXh);
    cudaGetSymbolAddress(&p_hsh,   g_HSh);
    cudaGetSymbolAddress(&p_ht,    g_hth);
    cudaGetSymbolAddress(&p_c,     g_c);

    cudaFuncSetAttribute(lstm_step_mma,
                         cudaFuncAttributeMaxDynamicSharedMemorySize,
                         DSM_BYTES);
    cudaFuncSetAttribute((hgemm_nt<1, IN_/2>),
                         cudaFuncAttributeMaxDynamicSharedMemorySize,
                         GSM_BYTES);
    cudaFuncSetAttribute((hgemm_nt<0, HW>),
                         cudaFuncAttributeMaxDynamicSharedMemorySize,
                         GSM_BYTES);

    // zero initial state; t=255 writes g_hth[0], re-zeroed on every replay.
    cudaMemsetAsync(p_ht, 0, (size_t)B_ * HW * sizeof(uint32_t));
    cudaMemsetAsync(p_c,  0, (size_t)B_ * H_ * sizeof(float));

    // Phase 0: pack weights + permuting fp16 converts for x and W_out
    pack_weights<<<G4_, 128>>>(W_f, W_i, W_c, W_o, b_f, b_i, b_c, b_o);
    {
        int nW = M_ * IN_ / 2;
        cvt_f2h_perm<<<(nW + 255) / 256, 256>>>(x, (uint32_t*)p_xh, nW);
        int wW = OUT_ * H_ / 2;
        cvt_f2h_perm<<<(wW + 255) / 256, 256>>>(W_out, (uint32_t*)p_wouth, wW);
    }

    // Phase 1: GXh = fp16( xh @ Wxph^T + bp )
    {
        dim3 grid(G4_ / 128, M_ / 128);
        hgemm_nt<1, IN_/2><<<grid, 256, GSM_BYTES>>>((const uint32_t*)p_xh,
                                                     (const uint32_t*)p_wxph,
                                                     (const float*)p_bp, p_gxh,
                                                     G4_);
    }

    // Phase 2: 256 recurrent steps (fp16 mma, JT=16 x Msplit=2, 3-stage)
    for (int t = 0; t < T_; t++) {
        dim3 grid(H_ / 16, 2);
        lstm_step_mma<<<grid, 256, DSM_BYTES>>>(t);
    }

    // Phase 3: out = HSh @ W_outh^T + b_out  (fp32 out)
    {
        dim3 grid(OUT_ / 128, M_ / 128);
        hgemm_nt<0, HW><<<grid, 256, GSM_BYTES>>>((const uint32_t*)p_hsh,
                                                  (const uint32_t*)p_wouth,
                                                  b_out, out, OUT_);
    }
}